// round 3
// baseline (speedup 1.0000x reference)
#include <cuda_runtime.h>
#include <cuda_bf16.h>

#define NPTS 32768
#define EDG  786432
#define KMAX 64
#define CIN  16
#define CMID 64
#define COUT 64

__device__ float g_prod[NPTS * CIN * CMID];
__device__ int   g_start[NPTS];
__device__ int   g_end[NPTS];

#define FMA2(d, a, b, c) \
    asm("fma.rn.f32x2 %0, %1, %2, %3;" : "=l"(d) : "l"(a), "l"(b), "l"(c))
#define PACK2(d, lo, hi) \
    asm("mov.b64 %0, {%1, %2};" : "=l"(d) : "f"(lo), "f"(hi))
#define UNPACK2(lo, hi, s) \
    asm("mov.b64 {%0, %1}, %2;" : "=f"(lo), "=f"(hi) : "l"(s))

__global__ void init_bounds_kernel() {
    int i = blockIdx.x * blockDim.x + threadIdx.x;
    if (i < NPTS) { g_start[i] = 0; g_end[i] = 0; }
}

__global__ void seg_bounds_kernel(const int* __restrict__ out_index) {
    int e = blockIdx.x * blockDim.x + threadIdx.x;
    if (e >= EDG) return;
    int v = out_index[e];
    if (e == 0) {
        g_start[v] = 0;
    } else {
        int pv = out_index[e - 1];
        if (pv != v) { g_start[v] = e; g_end[pv] = e; }
    }
    if (e == EDG - 1) g_end[v] = EDG;
}

__device__ __forceinline__ float celu1(float x) {
    return x > 0.f ? x : (__expf(x) - 1.f);
}

// One block (64 threads) per output point.
// Stage 1: threads (j = tid/16, c = tid%16), tile of 4 edges:
//   sh[j][c] = celu(pos_local . W1[:,c]),  sx[j][c] = x_in[i][c] / count
// Stage 2: thread tid = m; W2[:,m] held in 8 packed f32x2 registers;
//   d via 8 FFMA2 on h pairs; acc[16] as 8 packed f32x2.
__global__ __launch_bounds__(64) void edge_kernel(
    const float* __restrict__ x_in,
    const float* __restrict__ pos_in,
    const float* __restrict__ pos_out,
    const int*   __restrict__ in_index,
    const float* __restrict__ W1,
    const float* __restrict__ W2)
{
    __shared__ __align__(16) float sW1[48];
    __shared__ __align__(16) float sh[4][CIN];
    __shared__ __align__(16) float sx[4][CIN];

    const int tid = threadIdx.x;
    const int n   = blockIdx.x;

    if (tid < 48) sW1[tid] = W1[tid];

    // W2 column m in packed registers (coalesced global loads)
    const int m = tid;
    unsigned long long w2p[8];
    #pragma unroll
    for (int cp = 0; cp < 8; cp++) {
        float lo = W2[(2 * cp) * CMID + m];
        float hi = W2[(2 * cp + 1) * CMID + m];
        PACK2(w2p[cp], lo, hi);
    }

    const int s   = g_start[n];
    const int e   = g_end[n];
    const int cnt = e - s;
    const float inv = (cnt > 0) ? (1.f / (float)cnt) : 0.f;
    const int use = (cnt < KMAX) ? cnt : KMAX;

    const float pox = pos_out[3 * n + 0];
    const float poy = pos_out[3 * n + 1];
    const float poz = pos_out[3 * n + 2];

    unsigned long long accp[8];
    #pragma unroll
    for (int cp = 0; cp < 8; cp++) accp[cp] = 0ULL;

    const int j = tid >> 4;
    const int c = tid & 15;

    __syncthreads();

    for (int base = 0; base < use; base += 4) {
        // ---- stage 1: gather + first layer ----
        int eidx = base + j;
        float hv = 0.f, xv = 0.f;
        if (eidx < use) {
            int i = in_index[s + eidx];
            float p0 = pos_in[3 * i + 0] - pox;
            float p1 = pos_in[3 * i + 1] - poy;
            float p2 = pos_in[3 * i + 2] - poz;
            hv = celu1(p0 * sW1[c] + p1 * sW1[16 + c] + p2 * sW1[32 + c]);
            xv = x_in[i * CIN + c] * inv;
        }
        sh[j][c] = hv;
        sx[j][c] = xv;
        __syncthreads();

        // ---- stage 2: packed second layer + outer product ----
        #pragma unroll
        for (int jj = 0; jj < 4; jj++) {
            unsigned long long dp = 0ULL;
            #pragma unroll
            for (int cp = 0; cp < 8; cp++) {
                unsigned long long hp =
                    *(const unsigned long long*)&sh[jj][2 * cp];
                FMA2(dp, hp, w2p[cp], dp);
            }
            float dlo, dhi;
            UNPACK2(dlo, dhi, dp);
            float Mv = celu1(dlo + dhi);
            unsigned long long mvp;
            PACK2(mvp, Mv, Mv);
            #pragma unroll
            for (int cp = 0; cp < 8; cp++) {
                unsigned long long xp =
                    *(const unsigned long long*)&sx[jj][2 * cp];
                FMA2(accp[cp], xp, mvp, accp[cp]);
            }
        }
        __syncthreads();
    }

    float* gp = g_prod + (size_t)n * (CIN * CMID);
    #pragma unroll
    for (int cp = 0; cp < 8; cp++) {
        float lo, hi;
        UNPACK2(lo, hi, accp[cp]);
        gp[(2 * cp) * CMID + tid]     = lo;
        gp[(2 * cp + 1) * CMID + tid] = hi;
    }
}

// out[n][o] = sum_q prod[n][q] * W3[q][o] + b3[o]
// 64x64 tile, 256 threads, 4x4 per thread, packed over k-pairs via FFMA2.
__global__ __launch_bounds__(256) void out_gemm_kernel(
    const float* __restrict__ W3,
    const float* __restrict__ b3,
    float* __restrict__ out)
{
    __shared__ __align__(16) float sA[64][72];    // [row][k], k-contiguous
    __shared__ __align__(16) float sBT[64][66];   // [o][k],   k-contiguous

    const int tid = threadIdx.x;
    const int tc  = tid & 15;       // col group (o = tc*4 .. +3)
    const int tr  = tid >> 4;       // row group (r = tr*4 .. +3)
    const int n0  = blockIdx.x * 64;

    unsigned long long accP[4][4];
    #pragma unroll
    for (int i = 0; i < 4; i++)
        #pragma unroll
        for (int jj = 0; jj < 4; jj++) accP[i][jj] = 0ULL;

    for (int kt = 0; kt < 16; kt++) {
        const int k0 = kt * 64;
        #pragma unroll
        for (int it = 0; it < 16; it++) {
            int lin = it * 256 + tid;
            int rr = lin >> 6, kk = lin & 63;
            sA[rr][kk] = g_prod[(size_t)(n0 + rr) * 1024 + k0 + kk];
        }
        #pragma unroll
        for (int it = 0; it < 16; it++) {
            int lin = it * 256 + tid;
            int kk = lin >> 6, oo = lin & 63;
            sBT[oo][kk] = W3[(size_t)(k0 + kk) * 64 + oo];
        }
        __syncthreads();

        #pragma unroll 8
        for (int kp = 0; kp < 32; kp++) {
            unsigned long long a[4], b[4];
            #pragma unroll
            for (int ii = 0; ii < 4; ii++)
                a[ii] = *(const unsigned long long*)&sA[tr * 4 + ii][2 * kp];
            #pragma unroll
            for (int jj = 0; jj < 4; jj++)
                b[jj] = *(const unsigned long long*)&sBT[tc * 4 + jj][2 * kp];
            #pragma unroll
            for (int ii = 0; ii < 4; ii++)
                #pragma unroll
                for (int jj = 0; jj < 4; jj++)
                    FMA2(accP[ii][jj], a[ii], b[jj], accP[ii][jj]);
        }
        __syncthreads();
    }

    #pragma unroll
    for (int ii = 0; ii < 4; ii++) {
        int row = n0 + tr * 4 + ii;
        float4 r;
        float lo, hi;
        UNPACK2(lo, hi, accP[ii][0]); r.x = lo + hi + b3[tc * 4 + 0];
        UNPACK2(lo, hi, accP[ii][1]); r.y = lo + hi + b3[tc * 4 + 1];
        UNPACK2(lo, hi, accP[ii][2]); r.z = lo + hi + b3[tc * 4 + 2];
        UNPACK2(lo, hi, accP[ii][3]); r.w = lo + hi + b3[tc * 4 + 3];
        *(float4*)&out[(size_t)row * 64 + tc * 4] = r;
    }
}

extern "C" void kernel_launch(void* const* d_in, const int* in_sizes, int n_in,
                              void* d_out, int out_size) {
    const float* x_in      = (const float*)d_in[0];
    const float* pos_in    = (const float*)d_in[1];
    const float* pos_out   = (const float*)d_in[2];
    const int*   in_index  = (const int*)d_in[3];
    const int*   out_index = (const int*)d_in[4];
    const float* W1        = (const float*)d_in[5];
    const float* W2        = (const float*)d_in[6];
    const float* W3        = (const float*)d_in[7];
    const float* b3        = (const float*)d_in[8];
    float* out = (float*)d_out;

    init_bounds_kernel<<<NPTS / 256, 256>>>();
    seg_bounds_kernel<<<EDG / 256, 256>>>(out_index);
    edge_kernel<<<NPTS, 64>>>(x_in, pos_in, pos_out, in_index, W1, W2);
    out_gemm_kernel<<<NPTS / 64, 256>>>(W3, b3, out);
}

// round 5
// speedup vs baseline: 1.6249x; 1.6249x over previous
#include <cuda_runtime.h>
#include <cuda_bf16.h>
#include <cstdint>

#define NPTS 32768
#define EDG  786432
#define KMAX 64
#define CIN  16
#define CMID 64
#define COUT 64
#define QDIM 1024            // CIN*CMID

// bf16 split scratch: product matrix [N][QDIM] as hi+lo (k-contig rows)
__device__ __nv_bfloat16 g_prod_hi[NPTS * QDIM];
__device__ __nv_bfloat16 g_prod_lo[NPTS * QDIM];
__device__ __nv_bfloat16 g_w3t_hi[COUT * QDIM];   // [o][k]
__device__ __nv_bfloat16 g_w3t_lo[COUT * QDIM];
__device__ int g_start[NPTS];
__device__ int g_end[NPTS];

// ---------------- packed fp32 helpers ----------------
#define FMA2(d, a, b, c) \
    asm("fma.rn.f32x2 %0, %1, %2, %3;" : "=l"(d) : "l"(a), "l"(b), "l"(c))
#define PACK2(d, lo, hi) \
    asm("mov.b64 %0, {%1, %2};" : "=l"(d) : "f"(lo), "f"(hi))
#define UNPACK2(lo, hi, s) \
    asm("mov.b64 {%0, %1}, %2;" : "=f"(lo), "=f"(hi) : "l"(s))

// ---------------- mma helpers ----------------
__device__ __forceinline__ uint32_t smem_u32(const void* p) {
    uint32_t a;
    asm("{ .reg .u64 t; cvta.to.shared.u64 t, %1; cvt.u32.u64 %0, t; }"
        : "=r"(a) : "l"(p));
    return a;
}

#define LDSM_X4(r0, r1, r2, r3, addr) \
    asm volatile("ldmatrix.sync.aligned.m8n8.x4.shared.b16 {%0,%1,%2,%3}, [%4];" \
        : "=r"(r0), "=r"(r1), "=r"(r2), "=r"(r3) : "r"(addr))

#define MMA16816(d, a, b0, b1) \
    asm volatile("mma.sync.aligned.m16n8k16.row.col.f32.bf16.bf16.f32 " \
        "{%0,%1,%2,%3}, {%4,%5,%6,%7}, {%8,%9}, {%0,%1,%2,%3};" \
        : "+f"((d)[0]), "+f"((d)[1]), "+f"((d)[2]), "+f"((d)[3]) \
        : "r"((a)[0]), "r"((a)[1]), "r"((a)[2]), "r"((a)[3]), "r"(b0), "r"(b1))

__device__ __forceinline__ void split_bf16(float v, __nv_bfloat16& h, __nv_bfloat16& l) {
    h = __float2bfloat16(v);
    l = __float2bfloat16(v - __bfloat162float(h));
}

// ---------------- prep kernels ----------------
__global__ void init_bounds_kernel() {
    int i = blockIdx.x * blockDim.x + threadIdx.x;
    if (i < NPTS) { g_start[i] = 0; g_end[i] = 0; }
}

__global__ void seg_bounds_kernel(const int* __restrict__ out_index) {
    int e = blockIdx.x * blockDim.x + threadIdx.x;
    if (e >= EDG) return;
    int v = out_index[e];
    if (e == 0) {
        g_start[v] = 0;
    } else {
        int pv = out_index[e - 1];
        if (pv != v) { g_start[v] = e; g_end[pv] = e; }
    }
    if (e == EDG - 1) g_end[v] = EDG;
}

__global__ void w3_prep_kernel(const float* __restrict__ W3) {
    int i = blockIdx.x * blockDim.x + threadIdx.x;   // 65536, k-major in W3
    int k = i >> 6, o = i & 63;
    __nv_bfloat16 h, l;
    split_bf16(W3[i], h, l);
    g_w3t_hi[o * QDIM + k] = h;
    g_w3t_lo[o * QDIM + k] = l;
}

__device__ __forceinline__ float celu1(float x) {
    return x > 0.f ? x : (__expf(x) - 1.f);
}

// ---------------- edge kernel ----------------
__global__ __launch_bounds__(64) void edge_kernel(
    const float* __restrict__ x_in,
    const float* __restrict__ pos_in,
    const float* __restrict__ pos_out,
    const int*   __restrict__ in_index,
    const float* __restrict__ W1,
    const float* __restrict__ W2)
{
    __shared__ __align__(16) float sW1[48];
    __shared__ __align__(16) float sh[4][CIN];
    __shared__ __align__(16) float sx[4][CIN];

    const int tid = threadIdx.x;
    const int n   = blockIdx.x;

    if (tid < 48) sW1[tid] = W1[tid];

    const int m = tid;
    unsigned long long w2p[8];
    #pragma unroll
    for (int cp = 0; cp < 8; cp++) {
        float lo = W2[(2 * cp) * CMID + m];
        float hi = W2[(2 * cp + 1) * CMID + m];
        PACK2(w2p[cp], lo, hi);
    }

    const int s   = g_start[n];
    const int e   = g_end[n];
    const int cnt = e - s;
    const float inv = (cnt > 0) ? (1.f / (float)cnt) : 0.f;
    const int use = (cnt < KMAX) ? cnt : KMAX;

    const float pox = pos_out[3 * n + 0];
    const float poy = pos_out[3 * n + 1];
    const float poz = pos_out[3 * n + 2];

    unsigned long long accp[8];
    #pragma unroll
    for (int cp = 0; cp < 8; cp++) accp[cp] = 0ULL;

    const int j = tid >> 4;
    const int c = tid & 15;

    __syncthreads();

    for (int base = 0; base < use; base += 4) {
        int eidx = base + j;
        float hv = 0.f, xv = 0.f;
        if (eidx < use) {
            int i = in_index[s + eidx];
            float p0 = pos_in[3 * i + 0] - pox;
            float p1 = pos_in[3 * i + 1] - poy;
            float p2 = pos_in[3 * i + 2] - poz;
            hv = celu1(p0 * sW1[c] + p1 * sW1[16 + c] + p2 * sW1[32 + c]);
            xv = x_in[i * CIN + c] * inv;
        }
        sh[j][c] = hv;
        sx[j][c] = xv;
        __syncthreads();

        #pragma unroll
        for (int jj = 0; jj < 4; jj++) {
            unsigned long long dp = 0ULL;
            #pragma unroll
            for (int cp = 0; cp < 8; cp++) {
                unsigned long long hp = *(const unsigned long long*)&sh[jj][2 * cp];
                FMA2(dp, hp, w2p[cp], dp);
            }
            float dlo, dhi;
            UNPACK2(dlo, dhi, dp);
            float Mv = celu1(dlo + dhi);
            unsigned long long mvp;
            PACK2(mvp, Mv, Mv);
            #pragma unroll
            for (int cp = 0; cp < 8; cp++) {
                unsigned long long xp = *(const unsigned long long*)&sx[jj][2 * cp];
                FMA2(accp[cp], xp, mvp, accp[cp]);
            }
        }
        __syncthreads();
    }

    const size_t rbase = (size_t)n * QDIM;
    #pragma unroll
    for (int cp = 0; cp < 8; cp++) {
        float lo, hi;
        UNPACK2(lo, hi, accp[cp]);
        __nv_bfloat16 h0, l0, h1, l1;
        split_bf16(lo, h0, l0);
        split_bf16(hi, h1, l1);
        g_prod_hi[rbase + (2 * cp) * CMID + tid]     = h0;
        g_prod_lo[rbase + (2 * cp) * CMID + tid]     = l0;
        g_prod_hi[rbase + (2 * cp + 1) * CMID + tid] = h1;
        g_prod_lo[rbase + (2 * cp + 1) * CMID + tid] = l1;
    }
}

// ---------------- tensor-core GEMM via mma.sync ----------------
// out[n][o] = sum_k prod[n][k] * W3t[o][k] + b3[o]
// CTA: 256 thr / 8 warps; tile M=128, N=64; K chunk 64.
// Split bf16: D = Ah*Bh + Ah*Bl + Al*Bh  (fp32 accum).
#define TILE_K   64
#define PAD      8
#define ROWW     (TILE_K + PAD)                  // 72 bf16 per staged row
#define OFF_A_HI 0
#define OFF_A_LO (128 * ROWW * 2)                // 18432
#define OFF_B_HI (2 * 128 * ROWW * 2)            // 36864
#define OFF_B_LO (2 * 128 * ROWW * 2 + 64 * ROWW * 2)
#define GEMM_SMEM (2 * 128 * ROWW * 2 + 2 * 64 * ROWW * 2)   // 55296

__global__ __launch_bounds__(256) void mma_gemm_kernel(
    const float* __restrict__ b3,
    float* __restrict__ out)
{
    extern __shared__ __align__(16) char smem[];
    const uint32_t sbase = smem_u32(smem);
    const int tid  = threadIdx.x;
    const int wid  = tid >> 5;
    const int lane = tid & 31;
    const int n0   = blockIdx.x * 128;

    const __nv_bfloat16* gA_hi = g_prod_hi + (size_t)n0 * QDIM;
    const __nv_bfloat16* gA_lo = g_prod_lo + (size_t)n0 * QDIM;

    float acc[8][4];
    #pragma unroll
    for (int t = 0; t < 8; t++)
        #pragma unroll
        for (int i = 0; i < 4; i++) acc[t][i] = 0.f;

    // ldmatrix source addresses (per lane)
    const int a_row  = wid * 16 + (lane & 15);
    const int a_koff = (lane >> 4) * 8;
    const int b_n    = (lane & 7) + ((lane & 16) ? 8 : 0);
    const int b_koff = (lane & 8) ? 8 : 0;

    const uint32_t aHiAddr = sbase + OFF_A_HI + (uint32_t)(a_row * ROWW + a_koff) * 2;
    const uint32_t aLoAddr = sbase + OFF_A_LO + (uint32_t)(a_row * ROWW + a_koff) * 2;
    const uint32_t bHiAddr = sbase + OFF_B_HI + (uint32_t)(b_n * ROWW + b_koff) * 2;
    const uint32_t bLoAddr = sbase + OFF_B_LO + (uint32_t)(b_n * ROWW + b_koff) * 2;

    for (int kt = 0; kt < QDIM / TILE_K; kt++) {
        const int k0 = kt * TILE_K;

        // stage A (128 x 64 bf16 hi+lo): 4096 u32 each, 16 per thread
        #pragma unroll
        for (int it = 0; it < 16; it++) {
            int i = it * 256 + tid;
            int row = i >> 5, kk = i & 31;           // kk: u32 index (2 bf16)
            uint32_t dst = (uint32_t)(row * ROWW + kk * 2) * 2;
            size_t src = (size_t)row * QDIM + k0 + kk * 2;
            *(uint32_t*)(smem + OFF_A_HI + dst) = *(const uint32_t*)(gA_hi + src);
            *(uint32_t*)(smem + OFF_A_LO + dst) = *(const uint32_t*)(gA_lo + src);
        }
        // stage B (64 x 64 bf16 hi+lo): 2048 u32 each, 8 per thread
        #pragma unroll
        for (int it = 0; it < 8; it++) {
            int i = it * 256 + tid;
            int o = i >> 5, kk = i & 31;
            uint32_t dst = (uint32_t)(o * ROWW + kk * 2) * 2;
            size_t src = (size_t)o * QDIM + k0 + kk * 2;
            *(uint32_t*)(smem + OFF_B_HI + dst) = *(const uint32_t*)(g_w3t_hi + src);
            *(uint32_t*)(smem + OFF_B_LO + dst) = *(const uint32_t*)(g_w3t_lo + src);
        }
        __syncthreads();

        #pragma unroll
        for (int ks = 0; ks < 4; ks++) {
            const uint32_t kb = (uint32_t)(ks * 16) * 2;
            uint32_t ah[4], al[4];
            LDSM_X4(ah[0], ah[1], ah[2], ah[3], aHiAddr + kb);
            LDSM_X4(al[0], al[1], al[2], al[3], aLoAddr + kb);

            uint32_t bh[4][4], bl[4][4];
            #pragma unroll
            for (int p = 0; p < 4; p++) {
                const uint32_t nb = (uint32_t)(p * 16 * ROWW) * 2;
                LDSM_X4(bh[p][0], bh[p][1], bh[p][2], bh[p][3], bHiAddr + nb + kb);
                LDSM_X4(bl[p][0], bl[p][1], bl[p][2], bl[p][3], bLoAddr + nb + kb);
            }
            #pragma unroll
            for (int p = 0; p < 4; p++) {
                MMA16816(acc[2 * p],     ah, bh[p][0], bh[p][1]);
                MMA16816(acc[2 * p + 1], ah, bh[p][2], bh[p][3]);
                MMA16816(acc[2 * p],     ah, bl[p][0], bl[p][1]);
                MMA16816(acc[2 * p + 1], ah, bl[p][2], bl[p][3]);
                MMA16816(acc[2 * p],     al, bh[p][0], bh[p][1]);
                MMA16816(acc[2 * p + 1], al, bh[p][2], bh[p][3]);
            }
        }
        __syncthreads();
    }

    // epilogue: m16n8 D frag: d0,d1 -> row lane/4, cols (lane%4)*2 +0/1;
    //           d2,d3 -> row lane/4 + 8
    const int r0 = n0 + wid * 16 + (lane >> 2);
    const int cbase = (lane & 3) * 2;
    #pragma unroll
    for (int t = 0; t < 8; t++) {
        int col = t * 8 + cbase;
        float b0 = b3[col], b1 = b3[col + 1];
        out[(size_t)r0 * COUT + col]           = acc[t][0] + b0;
        out[(size_t)r0 * COUT + col + 1]       = acc[t][1] + b1;
        out[(size_t)(r0 + 8) * COUT + col]     = acc[t][2] + b0;
        out[(size_t)(r0 + 8) * COUT + col + 1] = acc[t][3] + b1;
    }
}

extern "C" void kernel_launch(void* const* d_in, const int* in_sizes, int n_in,
                              void* d_out, int out_size) {
    const float* x_in      = (const float*)d_in[0];
    const float* pos_in    = (const float*)d_in[1];
    const float* pos_out   = (const float*)d_in[2];
    const int*   in_index  = (const int*)d_in[3];
    const int*   out_index = (const int*)d_in[4];
    const float* W1        = (const float*)d_in[5];
    const float* W2        = (const float*)d_in[6];
    const float* W3        = (const float*)d_in[7];
    const float* b3        = (const float*)d_in[8];
    float* out = (float*)d_out;

    cudaFuncSetAttribute(mma_gemm_kernel,
                         cudaFuncAttributeMaxDynamicSharedMemorySize, GEMM_SMEM);

    init_bounds_kernel<<<NPTS / 256, 256>>>();
    seg_bounds_kernel<<<EDG / 256, 256>>>(out_index);
    w3_prep_kernel<<<(QDIM * COUT) / 256, 256>>>(W3);
    edge_kernel<<<NPTS, 64>>>(x_in, pos_in, pos_out, in_index, W1, W2);
    mma_gemm_kernel<<<NPTS / 128, 256, GEMM_SMEM>>>(b3, out);
}